// round 1
// baseline (speedup 1.0000x reference)
#include <cuda_runtime.h>

// Problem constants
#define BATCH   4
#define SEQ     2048
#define INF     4096
#define OUTF    4096
#define RANK    16
// SCALING = ALPHA/RANK = 16/16 = 1.0f  (multiply elided)

// Phase-1 tiling
#define SPLITS      8
#define K_PER_SPLIT (INF / SPLITS)   // 512
#define CHUNK       64
#define ROWS1       128
#define T1          128

// Phase-2 tiling
#define T2          128
#define ROWS2       128
#define O_PER_THR   4
#define OTILE       (T2 * O_PER_THR) // 512

// Scratch: split partials of Bx. Slot s=0 also holds the reduced sum.
__device__ float g_bx[SPLITS * BATCH * SEQ * RANK];  // 4 MB

// ---------------------------------------------------------------------------
// Phase 1: Bx_partial[s][b][n][r] = sum_{i in split s} x[b][n][i] * B[aid][r][i]
// Block: 128 threads, 128 rows, 512 K-columns (8 chunks of 64).
// ---------------------------------------------------------------------------
__global__ __launch_bounds__(T1) void lora_phase1(
    const float* __restrict__ x,
    const float* __restrict__ Bw,
    const int*   __restrict__ ids)
{
    __shared__ float4 xs[ROWS1][CHUNK / 4 + 1];  // [128][17] float4 — pad kills conflicts
    __shared__ float4 bs[RANK][CHUNK / 4];       // [16][16] float4

    const int tid = threadIdx.x;
    const int n0  = blockIdx.x * ROWS1;
    const int b   = blockIdx.y;
    const int s   = blockIdx.z;
    const int aid = ids[b];
    const int k0  = s * K_PER_SPLIT;

    const float* xbase = x  + (size_t)b * SEQ * INF;
    const float* Bbase = Bw + (size_t)aid * RANK * INF;

    float acc[RANK];
#pragma unroll
    for (int r = 0; r < RANK; ++r) acc[r] = 0.0f;

    const int jr = tid & 15;   // float4 column index within chunk
    const int rr = tid >> 4;   // 0..7

    for (int c0 = k0; c0 < k0 + K_PER_SPLIT; c0 += CHUNK) {
        // Cooperative coalesced load of x tile: 128 rows x 16 float4
#pragma unroll
        for (int k = 0; k < ROWS1 / 8; ++k) {
            const int row = rr + k * 8;
            const float4* src =
                (const float4*)(xbase + (size_t)(n0 + row) * INF + c0);
            xs[row][jr] = src[jr];
        }
        // B tile: 16 rows x 16 float4
#pragma unroll
        for (int k = 0; k < 2; ++k) {
            const int r = rr + k * 8;
            const float4* src = (const float4*)(Bbase + (size_t)r * INF + c0);
            bs[r][jr] = src[jr];
        }
        __syncthreads();

        // Thread = one sequence row; B loads are warp-uniform broadcasts.
#pragma unroll 4
        for (int j = 0; j < CHUNK / 4; ++j) {
            const float4 xv = xs[tid][j];
#pragma unroll
            for (int r = 0; r < RANK; ++r) {
                const float4 bv = bs[r][j];
                acc[r] += xv.x * bv.x + xv.y * bv.y + xv.z * bv.z + xv.w * bv.w;
            }
        }
        __syncthreads();
    }

    float4* d4 = (float4*)(g_bx +
        (((size_t)s * BATCH + b) * SEQ + (n0 + tid)) * RANK);
    d4[0] = make_float4(acc[0],  acc[1],  acc[2],  acc[3]);
    d4[1] = make_float4(acc[4],  acc[5],  acc[6],  acc[7]);
    d4[2] = make_float4(acc[8],  acc[9],  acc[10], acc[11]);
    d4[3] = make_float4(acc[12], acc[13], acc[14], acc[15]);
}

// ---------------------------------------------------------------------------
// Reduce the 8 split partials into slot s=0 (deterministic, no atomics).
// ---------------------------------------------------------------------------
__global__ void lora_reduce()
{
    const int total = BATCH * SEQ * RANK / 4;  // 32768 float4
    const int idx = blockIdx.x * blockDim.x + threadIdx.x;
    if (idx >= total) return;
    float4* p = (float4*)g_bx;
    float4 a = p[idx];
#pragma unroll
    for (int s = 1; s < SPLITS; ++s) {
        const float4 v = p[(size_t)s * total + idx];
        a.x += v.x; a.y += v.y; a.z += v.z; a.w += v.w;
    }
    p[idx] = a;
}

// ---------------------------------------------------------------------------
// Phase 2: out[b][n][o] = sum_r Bx[b][n][r] * A[aid][o][r]
// Thread owns 4 consecutive o-columns; its A rows (64 floats) live in regs.
// Per row: 4 broadcast LDG (Bx) + 64 FMA + 1 coalesced STG.128.
// ---------------------------------------------------------------------------
__device__ __forceinline__ float dot16(const float4* a,
                                       float4 b0, float4 b1,
                                       float4 b2, float4 b3)
{
    float s;
    s  = a[0].x * b0.x + a[0].y * b0.y + a[0].z * b0.z + a[0].w * b0.w;
    s += a[1].x * b1.x + a[1].y * b1.y + a[1].z * b1.z + a[1].w * b1.w;
    s += a[2].x * b2.x + a[2].y * b2.y + a[2].z * b2.z + a[2].w * b2.w;
    s += a[3].x * b3.x + a[3].y * b3.y + a[3].z * b3.z + a[3].w * b3.w;
    return s;
}

__global__ __launch_bounds__(T2) void lora_phase2(
    const float* __restrict__ Aw,
    const int*   __restrict__ ids,
    float*       __restrict__ out)
{
    const int tid = threadIdx.x;
    const int o   = blockIdx.x * OTILE + tid * O_PER_THR;
    const int n0  = blockIdx.y * ROWS2;
    const int b   = blockIdx.z;
    const int aid = ids[b];

    // A[aid][o..o+3][0..15] -> 16 float4 in registers (64 consecutive floats)
    const float4* A4 = (const float4*)(Aw + ((size_t)aid * OUTF + o) * RANK);
    float4 areg[16];
#pragma unroll
    for (int i = 0; i < 16; ++i) areg[i] = A4[i];

    const float4* bx   = (const float4*)g_bx + ((size_t)b * SEQ + n0) * (RANK / 4);
    float4*       out4 = (float4*)(out + ((size_t)b * SEQ + n0) * OUTF + o);

    for (int n = 0; n < ROWS2; ++n) {
        const float4 b0 = bx[n * 4 + 0];
        const float4 b1 = bx[n * 4 + 1];
        const float4 b2 = bx[n * 4 + 2];
        const float4 b3 = bx[n * 4 + 3];
        float4 res;
        res.x = dot16(&areg[0],  b0, b1, b2, b3);
        res.y = dot16(&areg[4],  b0, b1, b2, b3);
        res.z = dot16(&areg[8],  b0, b1, b2, b3);
        res.w = dot16(&areg[12], b0, b1, b2, b3);
        out4[(size_t)n * (OUTF / 4)] = res;   // SCALING == 1.0f
    }
}

// ---------------------------------------------------------------------------
extern "C" void kernel_launch(void* const* d_in, const int* in_sizes, int n_in,
                              void* d_out, int out_size)
{
    const float* x   = (const float*)d_in[0];   // [4,2048,4096]
    const float* Aw  = (const float*)d_in[1];   // [8,4096,16]
    const float* Bw  = (const float*)d_in[2];   // [8,16,4096]
    const int*   ids = (const int*)  d_in[3];   // [4]
    float*       out = (float*)d_out;           // [4,2048,4096]

    dim3 g1(SEQ / ROWS1, BATCH, SPLITS);        // (16,4,8) = 512 blocks
    lora_phase1<<<g1, T1>>>(x, Bw, ids);

    lora_reduce<<<(BATCH * SEQ * RANK / 4) / 256, 256>>>();

    dim3 g2(OUTF / OTILE, SEQ / ROWS2, BATCH);  // (8,16,4) = 512 blocks
    lora_phase2<<<g2, T2>>>(Aw, ids, out);
}

// round 2
// speedup vs baseline: 1.2103x; 1.2103x over previous
#include <cuda_runtime.h>

// Problem constants
#define BATCH   4
#define SEQ     2048
#define INF     4096
#define OUTF    4096
#define RANK    16
// SCALING = 16/16 = 1.0f (elided)

// Phase-1 tiling
#define SPLITS      16
#define K_PER_SPLIT (INF / SPLITS)      // 256
#define CHUNK       32
#define ROWS1       256                 // 2 rows per thread
#define T1          128
#define XPITCH      34                  // floats; even, %32==2 -> conflict-free LDS.64

// Phase-2 tiling
#define T2          128
#define ROWS2       128
#define OTILE       512                 // 4 outputs per thread

typedef unsigned long long ull;

// Scratch: split partials of Bx; slot 0 also holds the reduced sum. 8 MB.
__device__ float g_bx[SPLITS * BATCH * SEQ * RANK];

// ---- packed f32x2 FMA (PTX-only; ptxas never auto-fuses) ---------------
__device__ __forceinline__ void fma2(ull& d, ull a, ull b) {
    asm("fma.rn.f32x2 %0, %1, %2, %0;" : "+l"(d) : "l"(a), "l"(b));
}
__device__ __forceinline__ ull pack2(float lo, float hi) {
    ull d; asm("mov.b64 %0, {%1, %2};" : "=l"(d) : "f"(lo), "f"(hi)); return d;
}
__device__ __forceinline__ void unpack2(float& lo, float& hi, ull d) {
    asm("mov.b64 {%0, %1}, %2;" : "=f"(lo), "=f"(hi) : "l"(d));
}

// ---------------------------------------------------------------------------
// Phase 1: Bx_partial[s][b][n][r] = sum_{i in split s} x[b][n][i]*B[aid][r][i]
// 128 threads, 256 rows/block (2 per thread), K split 16 ways.
// Accumulators are k-paired f32x2; horizontal add at the end.
// ---------------------------------------------------------------------------
__global__ __launch_bounds__(T1) void lora_phase1(
    const float* __restrict__ x,
    const float* __restrict__ Bw,
    const int*   __restrict__ ids)
{
    __shared__ float xs[ROWS1 * XPITCH];        // 34816 B
    __shared__ float bs[RANK * CHUNK];          // 2048 B (pitch 32)

    const int tid = threadIdx.x;
    const int n0  = blockIdx.x * ROWS1;
    const int b   = blockIdx.y;
    const int s   = blockIdx.z;
    const int aid = ids[b];
    const int k0  = s * K_PER_SPLIT;

    const float* xbase = x  + (size_t)b * SEQ * INF;
    const float* Bbase = Bw + (size_t)aid * RANK * INF;

    ull accA[RANK], accB[RANK];
#pragma unroll
    for (int r = 0; r < RANK; ++r) { accA[r] = 0ull; accB[r] = 0ull; }

    for (int c0 = k0; c0 < k0 + K_PER_SPLIT; c0 += CHUNK) {
        // ---- stage x tile: 256 rows x 32 floats (coalesced LDG.128) ----
#pragma unroll
        for (int t = 0; t < (ROWS1 * CHUNK / 4) / T1; ++t) {   // 16 iters
            const int idx = t * T1 + tid;
            const int row = idx >> 3;
            const int j4  = idx & 7;
            const float4 v = *(const float4*)(xbase +
                (size_t)(n0 + row) * INF + c0 + 4 * j4);
            float* d = xs + row * XPITCH + 4 * j4;
            *(ull*)(d)     = pack2(v.x, v.y);
            *(ull*)(d + 2) = pack2(v.z, v.w);
        }
        // ---- stage B tile: 16 x 32 floats ----
        {
            const int row = tid >> 3;
            const int j4  = tid & 7;
            const float4 v = *(const float4*)(Bbase +
                (size_t)row * INF + c0 + 4 * j4);
            *(float4*)(bs + row * CHUNK + 4 * j4) = v;
        }
        __syncthreads();

        // ---- compute: thread = rows (tid, tid+128) ----
        const float* xrA = xs + tid * XPITCH;
        const float* xrB = xs + (tid + 128) * XPITCH;
#pragma unroll
        for (int j = 0; j < CHUNK / 4; ++j) {       // 8 iters of 4 k's
            const ull xa0 = *(const ull*)(xrA + 4 * j);
            const ull xa1 = *(const ull*)(xrA + 4 * j + 2);
            const ull xb0 = *(const ull*)(xrB + 4 * j);
            const ull xb1 = *(const ull*)(xrB + 4 * j + 2);
#pragma unroll
            for (int r = 0; r < RANK; ++r) {
                const ulonglong2 bv =
                    *(const ulonglong2*)(bs + r * CHUNK + 4 * j);  // broadcast
                fma2(accA[r], xa0, bv.x);
                fma2(accA[r], xa1, bv.y);
                fma2(accB[r], xb0, bv.x);
                fma2(accB[r], xb1, bv.y);
            }
        }
        __syncthreads();
    }

    // horizontal add + store both rows
    const size_t slot = (((size_t)s * BATCH + b) * SEQ);
    float4* dA = (float4*)(g_bx + (slot + n0 + tid) * RANK);
    float4* dB = (float4*)(g_bx + (slot + n0 + tid + 128) * RANK);
#pragma unroll
    for (int q = 0; q < 4; ++q) {
        float4 va, vb;
        float l0, h0, l1, h1, l2, h2, l3, h3;
        unpack2(l0, h0, accA[4 * q + 0]); unpack2(l1, h1, accA[4 * q + 1]);
        unpack2(l2, h2, accA[4 * q + 2]); unpack2(l3, h3, accA[4 * q + 3]);
        va = make_float4(l0 + h0, l1 + h1, l2 + h2, l3 + h3);
        unpack2(l0, h0, accB[4 * q + 0]); unpack2(l1, h1, accB[4 * q + 1]);
        unpack2(l2, h2, accB[4 * q + 2]); unpack2(l3, h3, accB[4 * q + 3]);
        vb = make_float4(l0 + h0, l1 + h1, l2 + h2, l3 + h3);
        dA[q] = va;
        dB[q] = vb;
    }
}

// ---------------------------------------------------------------------------
// Reduce 16 split partials into slot 0 (deterministic).
// ---------------------------------------------------------------------------
__global__ void lora_reduce()
{
    const int total = BATCH * SEQ * RANK / 4;      // 32768 float4
    const int idx = blockIdx.x * blockDim.x + threadIdx.x;
    if (idx >= total) return;
    float4* p = (float4*)g_bx;
    float4 a = p[idx];
#pragma unroll
    for (int s = 1; s < SPLITS; ++s) {
        const float4 v = p[(size_t)s * total + idx];
        a.x += v.x; a.y += v.y; a.z += v.z; a.w += v.w;
    }
    p[idx] = a;
}

// ---------------------------------------------------------------------------
// Phase 2: out[b][n][o] = sum_r Bx[b][n][r] * A[aid][o][r]
// Thread owns 4 outputs as 2 f32x2 pairs; A pairs in registers; Bx staged
// in shared pre-duplicated so each rank is half an LDS.128 broadcast.
// ---------------------------------------------------------------------------
#define BXP 9   // ulonglong2 pitch per row (padded)

__global__ __launch_bounds__(T2) void lora_phase2(
    const float* __restrict__ Aw,
    const int*   __restrict__ ids,
    float*       __restrict__ out)
{
    __shared__ ulonglong2 bxd[ROWS2 * BXP];     // 18 KB, [n][p]=(dup r=2p, dup r=2p+1)

    const int tid = threadIdx.x;
    const int o   = blockIdx.x * OTILE + tid * 4;
    const int n0  = blockIdx.y * ROWS2;
    const int b   = blockIdx.z;
    const int aid = ids[b];

    // ---- A[aid][o..o+3][0..15] -> 32 packed pairs in registers ----
    const float4* A4 = (const float4*)(Aw + ((size_t)aid * OUTF + o) * RANK);
    float ar[4][16];
#pragma unroll
    for (int q = 0; q < 4; ++q)
#pragma unroll
        for (int j = 0; j < 4; ++j) {
            const float4 v = A4[q * 4 + j];
            ar[q][4 * j] = v.x; ar[q][4 * j + 1] = v.y;
            ar[q][4 * j + 2] = v.z; ar[q][4 * j + 3] = v.w;
        }
    ull a01[16], a23[16];
#pragma unroll
    for (int r = 0; r < RANK; ++r) {
        a01[r] = pack2(ar[0][r], ar[1][r]);
        a23[r] = pack2(ar[2][r], ar[3][r]);
    }

    // ---- stage this block's Bx rows, duplicated ----
    {
        const float* src = g_bx + ((size_t)b * SEQ + n0 + tid) * RANK;
        float v[16];
#pragma unroll
        for (int j = 0; j < 4; ++j) {
            const float4 t = *(const float4*)(src + 4 * j);
            v[4 * j] = t.x; v[4 * j + 1] = t.y; v[4 * j + 2] = t.z; v[4 * j + 3] = t.w;
        }
#pragma unroll
        for (int p = 0; p < 8; ++p) {
            ulonglong2 e;
            e.x = pack2(v[2 * p], v[2 * p]);
            e.y = pack2(v[2 * p + 1], v[2 * p + 1]);
            bxd[tid * BXP + p] = e;
        }
    }
    __syncthreads();

    float4* out4 = (float4*)(out + ((size_t)b * SEQ + n0) * OUTF + o);

    for (int n = 0; n < ROWS2; ++n) {
        const ulonglong2* row = bxd + n * BXP;
        ull acc0 = 0ull, acc1 = 0ull;
#pragma unroll
        for (int p = 0; p < 8; ++p) {
            const ulonglong2 bb = row[p];            // broadcast
            fma2(acc0, a01[2 * p],     bb.x);
            fma2(acc0, a01[2 * p + 1], bb.y);
            fma2(acc1, a23[2 * p],     bb.x);
            fma2(acc1, a23[2 * p + 1], bb.y);
        }
        float4 res;
        unpack2(res.x, res.y, acc0);
        unpack2(res.z, res.w, acc1);
        out4[(size_t)n * (OUTF / 4)] = res;
    }
}

// ---------------------------------------------------------------------------
extern "C" void kernel_launch(void* const* d_in, const int* in_sizes, int n_in,
                              void* d_out, int out_size)
{
    const float* x   = (const float*)d_in[0];   // [4,2048,4096]
    const float* Aw  = (const float*)d_in[1];   // [8,4096,16]
    const float* Bw  = (const float*)d_in[2];   // [8,16,4096]
    const int*   ids = (const int*)  d_in[3];   // [4]
    float*       out = (float*)d_out;           // [4,2048,4096]

    dim3 g1(SEQ / ROWS1, BATCH, SPLITS);        // (8,4,16) = 512 blocks
    lora_phase1<<<g1, T1>>>(x, Bw, ids);

    lora_reduce<<<(BATCH * SEQ * RANK / 4) / 256, 256>>>();

    dim3 g2(OUTF / OTILE, SEQ / ROWS2, BATCH);  // (8,16,4) = 512 blocks
    lora_phase2<<<g2, T2>>>(Aw, ids, out);
}

// round 3
// speedup vs baseline: 1.4902x; 1.2313x over previous
#include <cuda_runtime.h>

#define BATCH 4
#define SEQ   2048
#define INF   4096
#define OUTF  4096
#define RANK  16
// SCALING = 16/16 = 1.0f (elided)

// ---- phase-1 tiling ----
#define SPLITS 8
#define KSPLIT (INF / SPLITS)        // 512
#define CHUNK  32
#define NCHUNK (KSPLIT / CHUNK)      // 16
#define ROWS1  256
#define T1     256                   // 2 rank-groups x 128 threads
#define XP     34                    // x pitch (floats): conflict-free LDS.64
#define XS_F   (ROWS1 * XP)          // 8704 floats
#define BS_F   (RANK * CHUNK)        // 512 floats
#define SMEM1  ((2 * XS_F + 2 * BS_F) * 4)   // 73728 B (dynamic, opt-in)

// ---- phase-2 tiling ----
#define T2    128
#define ROWS2 128
#define OPT   8                      // outputs per thread
#define OTILE (T2 * OPT)             // 1024
#define BXP   9

typedef unsigned long long ull;

__device__ float g_bx[SPLITS * BATCH * SEQ * RANK];   // 4 MB scratch

// ---- packed f32x2 helpers ------------------------------------------------
__device__ __forceinline__ void fma2(ull& d, ull a, ull b) {
    asm("fma.rn.f32x2 %0, %1, %2, %0;" : "+l"(d) : "l"(a), "l"(b));
}
__device__ __forceinline__ ull pack2(float lo, float hi) {
    ull d; asm("mov.b64 %0, {%1, %2};" : "=l"(d) : "f"(lo), "f"(hi)); return d;
}
__device__ __forceinline__ void unpack2(float& lo, float& hi, ull d) {
    asm("mov.b64 {%0, %1}, %2;" : "=f"(lo), "=f"(hi) : "l"(d));
}

// ---------------------------------------------------------------------------
// Phase 1: Bx_partial[s][b][n][r] = sum_{i in split s} x[b][n][i]*B[aid][r][i]
// 256 threads = 2 rank-groups (8 ranks each) x 128 threads (2 rows each).
// Double-buffered smem tiles; next-next chunk prefetched into registers.
// ---------------------------------------------------------------------------
#define LOADREGS(CC) do { const int c0_ = (CC);                               \
    _Pragma("unroll")                                                         \
    for (int w = 0; w < 8; ++w) {                                             \
        const int idx = w * T1 + tid;                                         \
        const int row = idx >> 3, j4 = idx & 7;                               \
        xr[w] = *(const float4*)(xbase + (size_t)(n0 + row) * INF + c0_ + 4 * j4); \
    }                                                                         \
    if (tid < 128) {                                                          \
        const int row = tid >> 3, j4 = tid & 7;                               \
        br = *(const float4*)(Bbase + (size_t)row * INF + c0_ + 4 * j4);      \
    } } while (0)

#define STSREGS(XS, BS) do {                                                  \
    _Pragma("unroll")                                                         \
    for (int w = 0; w < 8; ++w) {                                             \
        const int idx = w * T1 + tid;                                         \
        const int row = idx >> 3, j4 = idx & 7;                               \
        float* d_ = (XS) + row * XP + 4 * j4;                                 \
        ((ull*)d_)[0] = pack2(xr[w].x, xr[w].y);                              \
        ((ull*)d_)[1] = pack2(xr[w].z, xr[w].w);                              \
    }                                                                         \
    if (tid < 128) {                                                          \
        const int row = tid >> 3, j4 = tid & 7;                               \
        *(float4*)((BS) + row * CHUNK + 4 * j4) = br;                         \
    } } while (0)

#define COMPUTE(XS, BS) do {                                                  \
    const float* x0_ = (XS) + lt * XP;                                        \
    const float* x1_ = (XS) + (lt + 128) * XP;                                \
    const float* bg_ = (BS) + g * 8 * CHUNK;                                  \
    _Pragma("unroll")                                                         \
    for (int j = 0; j < 8; ++j) {                                             \
        const ull xa0 = *(const ull*)(x0_ + 4 * j);                           \
        const ull xa1 = *(const ull*)(x0_ + 4 * j + 2);                       \
        const ull xb0 = *(const ull*)(x1_ + 4 * j);                           \
        const ull xb1 = *(const ull*)(x1_ + 4 * j + 2);                       \
        _Pragma("unroll")                                                     \
        for (int r = 0; r < 8; ++r) {                                         \
            const ulonglong2 bv = *(const ulonglong2*)(bg_ + r * CHUNK + 4 * j); \
            fma2(acc0[r], xa0, bv.x); fma2(acc0[r], xa1, bv.y);               \
            fma2(acc1[r], xb0, bv.x); fma2(acc1[r], xb1, bv.y);               \
        }                                                                     \
    } } while (0)

__global__ __launch_bounds__(T1, 2) void lora_phase1(
    const float* __restrict__ x,
    const float* __restrict__ Bw,
    const int*   __restrict__ ids)
{
    extern __shared__ float sm[];
    float* const xs0 = sm;
    float* const xs1 = sm + XS_F;
    float* const bs0 = sm + 2 * XS_F;
    float* const bs1 = sm + 2 * XS_F + BS_F;

    const int tid = threadIdx.x;
    const int n0  = blockIdx.x * ROWS1;
    const int b   = blockIdx.y;
    const int s   = blockIdx.z;
    const int aid = ids[b];
    const int k0  = s * KSPLIT;
    const int g   = tid >> 7;     // rank group (0: r0-7, 1: r8-15)
    const int lt  = tid & 127;    // rows lt, lt+128

    const float* xbase = x  + (size_t)b * SEQ * INF;
    const float* Bbase = Bw + (size_t)aid * RANK * INF;

    float4 xr[8]; float4 br;
    ull acc0[8], acc1[8];
#pragma unroll
    for (int r = 0; r < 8; ++r) { acc0[r] = 0ull; acc1[r] = 0ull; }

    LOADREGS(k0);
    STSREGS(xs0, bs0);
    __syncthreads();
    LOADREGS(k0 + CHUNK);

#pragma unroll 1
    for (int c = 0; c < NCHUNK; c += 2) {
        COMPUTE(xs0, bs0);                           // chunk c
        __syncthreads();
        STSREGS(xs1, bs1);                           // stage chunk c+1
        if (c + 2 < NCHUNK) LOADREGS(k0 + (c + 2) * CHUNK);
        __syncthreads();
        COMPUTE(xs1, bs1);                           // chunk c+1
        if (c + 2 < NCHUNK) {
            __syncthreads();
            STSREGS(xs0, bs0);                       // stage chunk c+2
            if (c + 3 < NCHUNK) LOADREGS(k0 + (c + 3) * CHUNK);
            __syncthreads();
        }
    }

    // horizontal pair-add + store 8 ranks x 2 rows
    const size_t slot = ((size_t)s * BATCH + b) * SEQ;
    float* dA = g_bx + (slot + n0 + lt) * RANK + g * 8;
    float* dB = g_bx + (slot + n0 + lt + 128) * RANK + g * 8;
    float4 va0, va1, vb0, vb1;
    float l, h;
    unpack2(l, h, acc0[0]); va0.x = l + h;  unpack2(l, h, acc0[1]); va0.y = l + h;
    unpack2(l, h, acc0[2]); va0.z = l + h;  unpack2(l, h, acc0[3]); va0.w = l + h;
    unpack2(l, h, acc0[4]); va1.x = l + h;  unpack2(l, h, acc0[5]); va1.y = l + h;
    unpack2(l, h, acc0[6]); va1.z = l + h;  unpack2(l, h, acc0[7]); va1.w = l + h;
    unpack2(l, h, acc1[0]); vb0.x = l + h;  unpack2(l, h, acc1[1]); vb0.y = l + h;
    unpack2(l, h, acc1[2]); vb0.z = l + h;  unpack2(l, h, acc1[3]); vb0.w = l + h;
    unpack2(l, h, acc1[4]); vb1.x = l + h;  unpack2(l, h, acc1[5]); vb1.y = l + h;
    unpack2(l, h, acc1[6]); vb1.z = l + h;  unpack2(l, h, acc1[7]); vb1.w = l + h;
    ((float4*)dA)[0] = va0; ((float4*)dA)[1] = va1;
    ((float4*)dB)[0] = vb0; ((float4*)dB)[1] = vb1;
}

// ---------------------------------------------------------------------------
// Reduce the 8 split partials into slot 0 (deterministic).
// ---------------------------------------------------------------------------
__global__ void lora_reduce()
{
    const int total = BATCH * SEQ * RANK / 4;       // 32768 float4
    const int idx = blockIdx.x * blockDim.x + threadIdx.x;
    if (idx >= total) return;
    float4* p = (float4*)g_bx;
    float4 a = p[idx];
#pragma unroll
    for (int s = 1; s < SPLITS; ++s) {
        const float4 v = p[(size_t)s * total + idx];
        a.x += v.x; a.y += v.y; a.z += v.z; a.w += v.w;
    }
    p[idx] = a;
}

// ---------------------------------------------------------------------------
// Phase 2: out[b][n][o] = sum_r Bx[b][n][r] * A[aid][o][r]
// Thread owns 8 outputs as 4 f32x2 pairs; A pairs (64 ull) in registers;
// Bx staged in shared pre-duplicated. Per n: 8 LDS.128 + 64 fma2 + 2 STG.128.
// ---------------------------------------------------------------------------
__global__ __launch_bounds__(T2) void lora_phase2(
    const float* __restrict__ Aw,
    const int*   __restrict__ ids,
    float*       __restrict__ out)
{
    __shared__ ulonglong2 bxd[ROWS2 * BXP];         // 18 KB

    const int tid = threadIdx.x;
    const int o   = blockIdx.x * OTILE + tid * OPT;
    const int n0  = blockIdx.y * ROWS2;
    const int b   = blockIdx.z;
    const int aid = ids[b];

    // A pairs: ap[q][r] = (A[o+2q][r], A[o+2q+1][r])
    ull ap[4][16];
    {
        const float* Abase = Aw + ((size_t)aid * OUTF + o) * RANK;
#pragma unroll
        for (int q = 0; q < 4; ++q) {
            float e[16], f[16];
#pragma unroll
            for (int j = 0; j < 4; ++j) {
                const float4 v0 = *(const float4*)(Abase + (2 * q) * RANK + 4 * j);
                const float4 v1 = *(const float4*)(Abase + (2 * q + 1) * RANK + 4 * j);
                e[4 * j] = v0.x; e[4 * j + 1] = v0.y; e[4 * j + 2] = v0.z; e[4 * j + 3] = v0.w;
                f[4 * j] = v1.x; f[4 * j + 1] = v1.y; f[4 * j + 2] = v1.z; f[4 * j + 3] = v1.w;
            }
#pragma unroll
            for (int r = 0; r < 16; ++r) ap[q][r] = pack2(e[r], f[r]);
        }
    }

    // stage this block's Bx rows, duplicated (one row per thread)
    {
        const float* src = g_bx + ((size_t)b * SEQ + n0 + tid) * RANK;
        float v[16];
#pragma unroll
        for (int j = 0; j < 4; ++j) {
            const float4 t = *(const float4*)(src + 4 * j);
            v[4 * j] = t.x; v[4 * j + 1] = t.y; v[4 * j + 2] = t.z; v[4 * j + 3] = t.w;
        }
#pragma unroll
        for (int p = 0; p < 8; ++p) {
            ulonglong2 e;
            e.x = pack2(v[2 * p],     v[2 * p]);
            e.y = pack2(v[2 * p + 1], v[2 * p + 1]);
            bxd[tid * BXP + p] = e;
        }
    }
    __syncthreads();

    float4* outp = (float4*)(out + ((size_t)b * SEQ + n0) * OUTF + o);

#pragma unroll 2
    for (int n = 0; n < ROWS2; ++n) {
        const ulonglong2* row = bxd + n * BXP;
        ull a0 = 0ull, a1 = 0ull, a2 = 0ull, a3 = 0ull;
#pragma unroll
        for (int p = 0; p < 8; ++p) {
            const ulonglong2 bb = row[p];           // broadcast
            fma2(a0, ap[0][2 * p], bb.x); fma2(a0, ap[0][2 * p + 1], bb.y);
            fma2(a1, ap[1][2 * p], bb.x); fma2(a1, ap[1][2 * p + 1], bb.y);
            fma2(a2, ap[2][2 * p], bb.x); fma2(a2, ap[2][2 * p + 1], bb.y);
            fma2(a3, ap[3][2 * p], bb.x); fma2(a3, ap[3][2 * p + 1], bb.y);
        }
        float4 r0, r1;
        unpack2(r0.x, r0.y, a0); unpack2(r0.z, r0.w, a1);
        unpack2(r1.x, r1.y, a2); unpack2(r1.z, r1.w, a3);
        outp[(size_t)n * (OUTF / 4)]     = r0;
        outp[(size_t)n * (OUTF / 4) + 1] = r1;
    }
}

// ---------------------------------------------------------------------------
extern "C" void kernel_launch(void* const* d_in, const int* in_sizes, int n_in,
                              void* d_out, int out_size)
{
    const float* x   = (const float*)d_in[0];   // [4,2048,4096]
    const float* Aw  = (const float*)d_in[1];   // [8,4096,16]
    const float* Bw  = (const float*)d_in[2];   // [8,16,4096]
    const int*   ids = (const int*)  d_in[3];   // [4]
    float*       out = (float*)d_out;           // [4,2048,4096]

    cudaFuncSetAttribute(lora_phase1,
                         cudaFuncAttributeMaxDynamicSharedMemorySize, SMEM1);

    dim3 g1(SEQ / ROWS1, BATCH, SPLITS);        // (8,4,8) = 256 blocks
    lora_phase1<<<g1, T1, SMEM1>>>(x, Bw, ids);

    lora_reduce<<<(BATCH * SEQ * RANK / 4) / 256, 256>>>();

    dim3 g2(OUTF / OTILE, SEQ / ROWS2, BATCH);  // (4,16,4) = 256 blocks
    lora_phase2<<<g2, T2>>>(Aw, ids, out);
}